// round 11
// baseline (speedup 1.0000x reference)
#include <cuda_runtime.h>
#include <cstdint>

#define TT 512
#define BB 1024
#define VV 64
#define HH 100
#define H3 300
#define ROWS 4
#define NBLK 256
#define RT 640

// scratch: hidden states
__device__ float g_hidden[(size_t)TT * BB * HH];   // [t][b][j]  210 MB

typedef unsigned long long u64;

__device__ __forceinline__ u64 splat2(float w) {
    u64 r; asm("mov.b64 %0, {%1, %1};" : "=l"(r) : "f"(w)); return r;
}
__device__ __forceinline__ u64 fma2(u64 a, u64 b, u64 c) {
    u64 d; asm("fma.rn.f32x2 %0, %1, %2, %3;" : "=l"(d) : "l"(a), "l"(b), "l"(c)); return d;
}
__device__ __forceinline__ void unpk(u64 v, float& lo, float& hi) {
    asm("mov.b64 {%0, %1}, %2;" : "=f"(lo), "=f"(hi) : "l"(v));
}
__device__ __forceinline__ float tanh_fast(float x) {
    float y; asm("tanh.approx.f32 %0, %1;" : "=f"(y) : "f"(x)); return y;
}
__device__ __forceinline__ float sigmoid_f(float x) {
    return 1.0f / (1.0f + __expf(-x));
}

// ============================================================
// Fused recurrent kernel: gi (x-part) + gh (h-part) + gates, all in one.
// 256 blocks x 4 rows, 640 threads: (kq = tid/160 in [0,4), cp = tid%160 < 150).
// Each (kq,cp) handles cols {cp, cp+150}: gh over k in [kq*25,+25) (regs),
// gi over v in [kq*16,+16) (W_ih pre-splatted pairs in smem).
// ============================================================
#define OFF_WXD 0                 // [64][600] Wxd[v*600 + 2c + {0,1}] duplicated pairs
#define OFF_HS  38400             // [100][4]  hs[k*4+r]
#define OFF_H2  38800             // [4][100]  h2[r*100+j]
#define OFF_PG  39200             // [4][4][300] pg[kq*1200 + r*300 + c] (r/z: gi+gh; n: gh)
#define OFF_PN  44000             // [4][4][100] png[kq*400 + r*100 + jn] (n: gi part)
#define OFF_XS  45600             // [2][64][4] xs[buf*256 + v*4 + r]
#define OFF_BRZ 46112             // [200] b_ih+b_hh (r,z)
#define OFF_BIN 46312             // [100] b_ih n
#define OFF_BHN 46412             // [100] b_hh n
#define OFF_LEN 46512             // 4 ints
#define REC_SMEM_FLOATS (OFF_LEN + 4)
#define REC_SMEM_BYTES (REC_SMEM_FLOATS * 4)   // 186,064 B

__global__ void __launch_bounds__(RT, 1)
gru_fused_kernel(const float* __restrict__ x,
                 const float* __restrict__ h0,
                 const int*   __restrict__ lengths,
                 const float* __restrict__ W_ih,
                 const float* __restrict__ W_hh,
                 const float* __restrict__ b_ih,
                 const float* __restrict__ b_hh) {
    extern __shared__ float sm[];
    int* len_s = (int*)(sm + OFF_LEN);
    const int tid = threadIdx.x;
    const int row0 = blockIdx.x * ROWS;

    // W_ih [300][64] -> duplicated pairs Wxd[v*600 + 2c] = Wxd[..+1] = W_ih[c*64+v]
    for (int e = tid; e < H3 * VV; e += RT) {
        int c = e >> 6, v = e & 63;
        float w = W_ih[e];
        sm[OFF_WXD + v * 600 + 2 * c]     = w;
        sm[OFF_WXD + v * 600 + 2 * c + 1] = w;
    }
    for (int e = tid; e < 200; e += RT) sm[OFF_BRZ + e] = b_ih[e] + b_hh[e];
    if (tid < 100) {
        sm[OFF_BIN + tid] = b_ih[200 + tid];
        sm[OFF_BHN + tid] = b_hh[200 + tid];
    }
    for (int e = tid; e < ROWS * HH; e += RT) {
        int r = e / 100, j = e - r * 100;
        float hv = h0[(size_t)(row0 + r) * HH + j];
        sm[OFF_HS + j * ROWS + r] = hv;
        sm[OFF_H2 + r * HH + j]   = hv;
    }
    if (tid < ROWS) len_s[tid] = lengths[row0 + tid];

    // x tile for t=0 into buf 0: xs[v*4+r]
    if (tid < 64) {
        int r = tid >> 4, q = tid & 15;
        float4 px = *(const float4*)&x[((size_t)0 * BB + row0 + r) * VV + 4 * q];
        sm[OFF_XS + (4 * q + 0) * 4 + r] = px.x;
        sm[OFF_XS + (4 * q + 1) * 4 + r] = px.y;
        sm[OFF_XS + (4 * q + 2) * 4 + r] = px.z;
        sm[OFF_XS + (4 * q + 3) * 4 + r] = px.w;
    }

    const int kq = tid / 160;            // 0..3
    const int cp = tid - kq * 160;
    const bool act = (cp < 150);
    const int kbase = kq * 25;
    const int vbase = kq * 16;
    const bool ncol2 = (cp >= 50);       // col2 = cp+150 is an n-gate col

    // W_hh -> registers (25 consecutive per (thread, col))
    float wA[25], wB[25];
    if (act) {
        const float* pA = W_hh + cp * 100 + kbase;
        const float* pB = W_hh + (cp + 150) * 100 + kbase;
#pragma unroll
        for (int i = 0; i < 25; i++) { wA[i] = pA[i]; wB[i] = pB[i]; }
    }
    __syncthreads();

    int ml = len_s[0];
#pragma unroll
    for (int i = 1; i < ROWS; i++) ml = max(ml, len_s[i]);

    const u64 one2 = splat2(1.0f);

    for (int t = 0; t < ml; t++) {
        const int buf = t & 1;
        const int nbuf = buf ^ 1;

        // prefetch next x tile into regs (latency hidden under compute)
        float4 px;
        const bool pf = (tid < 64) && (t + 1 < ml);
        int pr = 0, pq = 0;
        if (pf) {
            pr = tid >> 4; pq = tid & 15;
            px = *(const float4*)&x[((size_t)(t + 1) * BB + row0 + pr) * VV + 4 * pq];
        }

        if (act) {
            // ---- gh: h-part over k in [kbase, kbase+25) ----
            const float* hsb = sm + OFF_HS + kbase * ROWS;
            u64 aH0[2], aH1[2];
            aH0[0] = 0; aH0[1] = 0; aH1[0] = 0; aH1[1] = 0;
#pragma unroll
            for (int i = 0; i < 25; i++) {
                u64 w0 = splat2(wA[i]);
                u64 w1 = splat2(wB[i]);
                ulonglong2 p = *(const ulonglong2*)(hsb + i * ROWS);
                aH0[0] = fma2(w0, p.x, aH0[0]); aH0[1] = fma2(w0, p.y, aH0[1]);
                aH1[0] = fma2(w1, p.x, aH1[0]); aH1[1] = fma2(w1, p.y, aH1[1]);
            }
            // ---- gi: x-part over v in [vbase, vbase+16) ----
            const float* wx0 = sm + OFF_WXD + 2 * cp;
            const float* wx1 = sm + OFF_WXD + 2 * (cp + 150);
            const float* xsb = sm + OFF_XS + buf * 256;
            u64 aX0[2], aX1[2];
            aX0[0] = 0; aX0[1] = 0; aX1[0] = 0; aX1[1] = 0;
#pragma unroll
            for (int i = 0; i < 16; i++) {
                int v = vbase + i;
                u64 w0 = *(const u64*)(wx0 + v * 600);
                u64 w1 = *(const u64*)(wx1 + v * 600);
                ulonglong2 xv = *(const ulonglong2*)(xsb + v * 4);
                aX0[0] = fma2(w0, xv.x, aX0[0]); aX0[1] = fma2(w0, xv.y, aX0[1]);
                aX1[0] = fma2(w1, xv.x, aX1[0]); aX1[1] = fma2(w1, xv.y, aX1[1]);
            }
            // ---- stores ----
            float* pgk = sm + OFF_PG + kq * 1200;
            float f0, f1;
            // col1 = cp (< 150 -> always r/z): combined gi+gh
            u64 c0 = fma2(one2, aX0[0], aH0[0]);
            u64 c1 = fma2(one2, aX0[1], aH0[1]);
            unpk(c0, f0, f1); pgk[0 * H3 + cp] = f0; pgk[1 * H3 + cp] = f1;
            unpk(c1, f0, f1); pgk[2 * H3 + cp] = f0; pgk[3 * H3 + cp] = f1;
            // col2 = cp+150
            if (!ncol2) {
                // c2 < 200: r/z -> combined
                u64 d0 = fma2(one2, aX1[0], aH1[0]);
                u64 d1 = fma2(one2, aX1[1], aH1[1]);
                unpk(d0, f0, f1); pgk[0 * H3 + cp + 150] = f0; pgk[1 * H3 + cp + 150] = f1;
                unpk(d1, f0, f1); pgk[2 * H3 + cp + 150] = f0; pgk[3 * H3 + cp + 150] = f1;
            } else {
                // c2 in [200,300): n-gate -> gh to pg, gi to png
                unpk(aH1[0], f0, f1); pgk[0 * H3 + cp + 150] = f0; pgk[1 * H3 + cp + 150] = f1;
                unpk(aH1[1], f0, f1); pgk[2 * H3 + cp + 150] = f0; pgk[3 * H3 + cp + 150] = f1;
                float* pnk = sm + OFF_PN + kq * 400 + (cp - 50);
                unpk(aX1[0], f0, f1); pnk[0 * HH] = f0; pnk[1 * HH] = f1;
                unpk(aX1[1], f0, f1); pnk[2 * HH] = f0; pnk[3 * HH] = f1;
            }
        }

        // stash prefetched x tile (visible after barrier)
        if (pf) {
            float* xd = sm + OFF_XS + nbuf * 256;
            xd[(4 * pq + 0) * 4 + pr] = px.x;
            xd[(4 * pq + 1) * 4 + pr] = px.y;
            xd[(4 * pq + 2) * 4 + pr] = px.z;
            xd[(4 * pq + 3) * 4 + pr] = px.w;
        }
        __syncthreads();

        // ---- gate phase: 400 outputs, o -> (r = o/100, j = o%100) ----
        if (tid < ROWS * HH) {
            int o = tid;
            int r = o / 100;
            int j = o - r * 100;
            const float* pgr = sm + OFF_PG + r * H3 + j;
            float s_r = pgr[0]   + pgr[1200]       + pgr[2400]       + pgr[3600];
            float s_z = pgr[100] + pgr[1200 + 100] + pgr[2400 + 100] + pgr[3600 + 100];
            float s_nh = pgr[200] + pgr[1200 + 200] + pgr[2400 + 200] + pgr[3600 + 200];
            const float* pnr = sm + OFF_PN + r * HH + j;
            float s_ni = pnr[0] + pnr[400] + pnr[800] + pnr[1200];
            float rg = sigmoid_f(s_r + sm[OFF_BRZ + j]);
            float zg = sigmoid_f(s_z + sm[OFF_BRZ + j + 100]);
            float hn = s_nh + sm[OFF_BHN + j];
            float in = s_ni + sm[OFF_BIN + j];
            float nv = tanh_fast(fmaf(rg, hn, in));
            float hold = sm[OFF_H2 + r * HH + j];
            float hnew = fmaf(zg, hold - nv, nv);
            float hout = (t < len_s[r]) ? hnew : hold;
            sm[OFF_H2 + r * HH + j] = hout;
            sm[OFF_HS + j * ROWS + r] = hout;
            g_hidden[((size_t)t * BB + row0 + r) * HH + j] = hout;
        }
        __syncthreads();
    }
}

// ============================================================
// Epilogue: software-pipelined, unchanged from R9 (best).
// ============================================================
struct QS {
    float h[4][4];
    bool act[4];
    bool any;
};

__device__ __forceinline__ void loadq(QS& s, int q, int lane,
                                      const int* __restrict__ lengths) {
    int rid0 = q * 4;
    int t  = q >> 8;
    int b0 = rid0 & 1023;
    int L0 = lengths[b0];
    s.any = (t < L0);
    if (!s.any) return;
    s.act[0] = true;
    s.act[1] = t < lengths[b0 + 1];
    s.act[2] = t < lengths[b0 + 2];
    s.act[3] = t < lengths[b0 + 3];
#pragma unroll
    for (int i = 0; i < 4; i++) {
        const float* hp = g_hidden + (size_t)(rid0 + i) * HH;
        s.h[i][0] = hp[lane];
        s.h[i][1] = hp[lane + 32];
        s.h[i][2] = hp[lane + 64];
        s.h[i][3] = (lane < 4) ? hp[lane + 96] : 0.0f;
    }
}

__device__ __forceinline__ void procq(const QS& s, int q, int w, int lane,
                                      const float* Wo, float bo0, float bo1,
                                      float (*hq)[HH * 4],
                                      float* __restrict__ out) {
    int rid0 = q * 4;
    float* op = out + (size_t)rid0 * VV;
#pragma unroll
    for (int i = 0; i < 4; i++) {
        hq[w][lane * 4 + i]        = s.h[i][0];
        hq[w][(lane + 32) * 4 + i] = s.h[i][1];
        hq[w][(lane + 64) * 4 + i] = s.h[i][2];
        if (lane < 4) hq[w][(lane + 96) * 4 + i] = s.h[i][3];
    }
    __syncwarp();
    float acc0[4] = {0.f, 0.f, 0.f, 0.f};
    float acc1[4] = {0.f, 0.f, 0.f, 0.f};
#pragma unroll 5
    for (int k = 0; k < HH; k++) {
        float4 hv = *(const float4*)&hq[w][k * 4];
        float w0 = Wo[k * VV + lane];
        float w1 = Wo[k * VV + lane + 32];
        acc0[0] = fmaf(hv.x, w0, acc0[0]); acc1[0] = fmaf(hv.x, w1, acc1[0]);
        acc0[1] = fmaf(hv.y, w0, acc0[1]); acc1[1] = fmaf(hv.y, w1, acc1[1]);
        acc0[2] = fmaf(hv.z, w0, acc0[2]); acc1[2] = fmaf(hv.z, w1, acc1[2]);
        acc0[3] = fmaf(hv.w, w0, acc0[3]); acc1[3] = fmaf(hv.w, w1, acc1[3]);
    }
#pragma unroll
    for (int i = 0; i < 4; i++) {
        if (!s.act[i]) continue;
        float l0 = acc0[i] + bo0;
        float l1 = acc1[i] + bo1;
        float m = fmaxf(l0, l1);
#pragma unroll
        for (int sh = 16; sh; sh >>= 1) m = fmaxf(m, __shfl_xor_sync(0xffffffffu, m, sh));
        float se = __expf(l0 - m) + __expf(l1 - m);
#pragma unroll
        for (int sh = 16; sh; sh >>= 1) se += __shfl_xor_sync(0xffffffffu, se, sh);
        float lse = m + __logf(se);
        op[i * VV + lane]      = l0 - lse;
        op[i * VV + lane + 32] = l1 - lse;
    }
    __syncwarp();
}

__global__ void __launch_bounds__(256)
gru_output_kernel(const int*   __restrict__ lengths,
                  const float* __restrict__ W_out,
                  const float* __restrict__ b_out,
                  float*       __restrict__ out) {
    __shared__ float Wo[HH * VV];
    __shared__ float bo[VV];
    __shared__ float hq[8][HH * 4];
    const int tid = threadIdx.x;
    for (int e = tid; e < VV * HH; e += 256) {
        int cc = e / 100, k = e - cc * 100;
        Wo[k * VV + cc] = W_out[e];
    }
    if (tid < VV) bo[tid] = b_out[tid];
    __syncthreads();

    const int w = tid >> 5;
    const int lane = tid & 31;
    const float bo0 = bo[lane];
    const float bo1 = bo[lane + 32];
    const int nquad = (TT * BB) / 4;
    const int stride = gridDim.x * 8;

    QS A, B;
    int q = blockIdx.x * 8 + w;
    if (q < nquad) loadq(A, q, lane, lengths);
    while (q < nquad) {
        int qn = q + stride;
        if (qn < nquad) loadq(B, qn, lane, lengths);
        if (A.any) procq(A, q, w, lane, Wo, bo0, bo1, hq, out);
        q = qn;
        if (q >= nquad) break;
        qn = q + stride;
        if (qn < nquad) loadq(A, qn, lane, lengths);
        if (B.any) procq(B, q, w, lane, Wo, bo0, bo1, hq, out);
        q = qn;
    }
}

extern "C" void kernel_launch(void* const* d_in, const int* in_sizes, int n_in,
                              void* d_out, int out_size) {
    const float* x      = (const float*)d_in[0];
    const float* h0     = (const float*)d_in[1];
    const int*   lens   = (const int*)  d_in[2];
    const float* W_ih   = (const float*)d_in[3];
    const float* W_hh   = (const float*)d_in[4];
    const float* b_ih   = (const float*)d_in[5];
    const float* b_hh   = (const float*)d_in[6];
    const float* W_out  = (const float*)d_in[7];
    const float* b_out  = (const float*)d_in[8];
    float* out = (float*)d_out;

    cudaFuncSetAttribute(gru_fused_kernel,
                         cudaFuncAttributeMaxDynamicSharedMemorySize, REC_SMEM_BYTES);

    cudaMemsetAsync(out, 0, (size_t)out_size * sizeof(float));
    gru_fused_kernel<<<NBLK, RT, REC_SMEM_BYTES>>>(x, h0, lens, W_ih, W_hh, b_ih, b_hh);
    gru_output_kernel<<<2048, 256>>>(lens, W_out, b_out, out);
}

// round 12
// speedup vs baseline: 1.2216x; 1.2216x over previous
#include <cuda_runtime.h>
#include <cstdint>

#define TT 512
#define BB 1024
#define VV 64
#define HH 100
#define H3 300
#define ROWS 4
#define NBLK 256
#define RT 640
#define PT 320

// device scratch
__device__ float g_hidden[(size_t)TT * BB * HH];   // [t][b][j]  210 MB
__device__ float g_gi[(size_t)TT * BB * H3];       // [t][b][c]  630 MB (biases folded)

typedef unsigned long long u64;

__device__ __forceinline__ u64 splat2(float w) {
    u64 r; asm("mov.b64 %0, {%1, %1};" : "=l"(r) : "f"(w)); return r;
}
__device__ __forceinline__ u64 pack2(float lo, float hi) {
    u64 r; asm("mov.b64 %0, {%1, %2};" : "=l"(r) : "f"(lo), "f"(hi)); return r;
}
__device__ __forceinline__ u64 fma2(u64 a, u64 b, u64 c) {
    u64 d; asm("fma.rn.f32x2 %0, %1, %2, %3;" : "=l"(d) : "l"(a), "l"(b), "l"(c)); return d;
}
__device__ __forceinline__ void unpk(u64 v, float& lo, float& hi) {
    asm("mov.b64 {%0, %1}, %2;" : "=f"(lo), "=f"(hi) : "l"(v));
}
__device__ __forceinline__ float tanh_fast(float x) {
    float y; asm("tanh.approx.f32 %0, %1;" : "=f"(y) : "f"(x)); return y;
}
__device__ __forceinline__ float sigmoid_f(float x) {
    return 1.0f / (1.0f + __expf(-x));
}

// ============================================================
// Pre-kernel v3: gi = x@W_ih^T + biases. LDS-wavefront-optimized:
// thread tile = 4 consecutive cols x 16 rows (32 FFMA2 per 8 LDS-wf).
// grid = 1024 (t = bid>>1, half = bid&1), 320 threads, 2 CTAs/SM.
// 8 passes of 64 rows, dead passes skipped.
// ============================================================
#define PRE_XS_STRIDE 68
#define PRE_XS_FLOATS (64 * PRE_XS_STRIDE)         // 4352
#define PRE_SMEM_FLOATS (19200 + 304 + PRE_XS_FLOATS)   // 23856 -> 95.4 KB
__global__ void __launch_bounds__(PT, 2)
gi_precompute_kernel(const float* __restrict__ x,
                     const int*   __restrict__ lengths,
                     const float* __restrict__ W_ih,
                     const float* __restrict__ b_ih,
                     const float* __restrict__ b_hh) {
    extern __shared__ float sm[];
    __shared__ int s_npass;
    float* Wih_s = sm;                     // [64][300] Wih_s[v*300+c]
    float* bs    = sm + 19200;             // [300]+pad
    float* xs    = sm + 19504;             // [64][68]  xs[v*68+row]

    const int tid = threadIdx.x;
    const int t = blockIdx.x >> 1;
    const int rbase = (blockIdx.x & 1) * 512;

    if (tid == 0) {
        int lo = 0, hi = BB;
        while (lo < hi) {
            int m = (lo + hi) >> 1;
            if (lengths[m] > t) lo = m + 1; else hi = m;
        }
        int na = lo - rbase;
        na = na < 0 ? 0 : (na > 512 ? 512 : na);
        s_npass = (na + 63) >> 6;
    }
    __syncthreads();
    const int npass = s_npass;
    if (npass == 0) return;

    for (int e = tid; e < H3 * VV; e += PT) {
        int c = e >> 6, v = e & 63;
        Wih_s[v * H3 + c] = W_ih[e];
    }
    for (int c = tid; c < H3; c += PT)
        bs[c] = b_ih[c] + ((c < 200) ? b_hh[c] : 0.0f);

    const size_t xrow0 = (size_t)t * BB + rbase;
    // pass 0 x tile: 64 rows, pairs
    for (int e = tid; e < 2048; e += PT) {
        int rp = e >> 6, v = e & 63;
        float lo = x[(xrow0 + 2 * rp) * VV + v];
        float hi = x[(xrow0 + 2 * rp + 1) * VV + v];
        *(u64*)(xs + v * PRE_XS_STRIDE + rp * 2) = pack2(lo, hi);
    }
    __syncthreads();

    const int rq = tid / 80;               // 0..3 -> 16 rows each
    const int cg = tid - rq * 80;
    const bool act = (cg < 75);
    const int c0 = cg * 4;
    float4 bq = make_float4(0.f, 0.f, 0.f, 0.f);
    if (act) bq = *(const float4*)(bs + c0);

    for (int pass = 0; pass < npass; pass++) {
        const bool has = (pass + 1 < npass);
        u64 pf[7];
        if (has) {
            const size_t base = (xrow0 + (pass + 1) * 64) * VV;
#pragma unroll
            for (int i = 0; i < 7; i++) {
                int e = tid + i * PT;
                if (e < 2048) {
                    int rp = e >> 6, v = e & 63;
                    float lo = x[base + (size_t)(2 * rp) * VV + v];
                    float hi = x[base + (size_t)(2 * rp + 1) * VV + v];
                    pf[i] = pack2(lo, hi);
                }
            }
        }
        if (act) {
            u64 a0[8], a1[8], a2[8], a3[8];
#pragma unroll
            for (int i = 0; i < 8; i++) { a0[i] = 0; a1[i] = 0; a2[i] = 0; a3[i] = 0; }
            const float* wv = Wih_s + c0;
            const float* xb = xs + rq * 16;
#pragma unroll 4
            for (int v = 0; v < VV; v++) {
                float4 w4 = *(const float4*)(wv + v * H3);
                u64 w0 = splat2(w4.x);
                u64 w1 = splat2(w4.y);
                u64 w2 = splat2(w4.z);
                u64 w3 = splat2(w4.w);
                const float* xr = xb + v * PRE_XS_STRIDE;
                ulonglong2 p0 = *(const ulonglong2*)(xr);
                ulonglong2 p1 = *(const ulonglong2*)(xr + 4);
                ulonglong2 p2 = *(const ulonglong2*)(xr + 8);
                ulonglong2 p3 = *(const ulonglong2*)(xr + 12);
                a0[0] = fma2(w0, p0.x, a0[0]); a0[1] = fma2(w0, p0.y, a0[1]);
                a0[2] = fma2(w0, p1.x, a0[2]); a0[3] = fma2(w0, p1.y, a0[3]);
                a0[4] = fma2(w0, p2.x, a0[4]); a0[5] = fma2(w0, p2.y, a0[5]);
                a0[6] = fma2(w0, p3.x, a0[6]); a0[7] = fma2(w0, p3.y, a0[7]);
                a1[0] = fma2(w1, p0.x, a1[0]); a1[1] = fma2(w1, p0.y, a1[1]);
                a1[2] = fma2(w1, p1.x, a1[2]); a1[3] = fma2(w1, p1.y, a1[3]);
                a1[4] = fma2(w1, p2.x, a1[4]); a1[5] = fma2(w1, p2.y, a1[5]);
                a1[6] = fma2(w1, p3.x, a1[6]); a1[7] = fma2(w1, p3.y, a1[7]);
                a2[0] = fma2(w2, p0.x, a2[0]); a2[1] = fma2(w2, p0.y, a2[1]);
                a2[2] = fma2(w2, p1.x, a2[2]); a2[3] = fma2(w2, p1.y, a2[3]);
                a2[4] = fma2(w2, p2.x, a2[4]); a2[5] = fma2(w2, p2.y, a2[5]);
                a2[6] = fma2(w2, p3.x, a2[6]); a2[7] = fma2(w2, p3.y, a2[7]);
                a3[0] = fma2(w3, p0.x, a3[0]); a3[1] = fma2(w3, p0.y, a3[1]);
                a3[2] = fma2(w3, p1.x, a3[2]); a3[3] = fma2(w3, p1.y, a3[3]);
                a3[4] = fma2(w3, p2.x, a3[4]); a3[5] = fma2(w3, p2.y, a3[5]);
                a3[6] = fma2(w3, p3.x, a3[6]); a3[7] = fma2(w3, p3.y, a3[7]);
            }
            const size_t rowg = xrow0 + pass * 64 + rq * 16;
#pragma unroll
            for (int rp = 0; rp < 8; rp++) {
                float f00, f01, f10, f11, f20, f21, f30, f31;
                unpk(a0[rp], f00, f01);
                unpk(a1[rp], f10, f11);
                unpk(a2[rp], f20, f21);
                unpk(a3[rp], f30, f31);
                float4 o0 = make_float4(f00 + bq.x, f10 + bq.y, f20 + bq.z, f30 + bq.w);
                float4 o1 = make_float4(f01 + bq.x, f11 + bq.y, f21 + bq.z, f31 + bq.w);
                *(float4*)&g_gi[(rowg + 2 * rp) * H3 + c0]     = o0;
                *(float4*)&g_gi[(rowg + 2 * rp + 1) * H3 + c0] = o1;
            }
        }
        __syncthreads();   // compute done before xs overwrite
        if (has) {
#pragma unroll
            for (int i = 0; i < 7; i++) {
                int e = tid + i * PT;
                if (e < 2048) {
                    int rp = e >> 6, v = e & 63;
                    *(u64*)(xs + v * PRE_XS_STRIDE + rp * 2) = pf[i];
                }
            }
        }
        __syncthreads();
    }
}

// ============================================================
// Recurrent kernel: unchanged from R9 (best).
// ============================================================
#define OFF_HS 0
#define OFF_H2 400
#define OFF_PG 800
#define OFF_GI 5600
#define OFF_BHN 8000
#define OFF_LEN 8100
#define REC_SMEM_FLOATS (OFF_LEN + 4)
#define REC_SMEM_BYTES (REC_SMEM_FLOATS * 4)

__global__ void __launch_bounds__(RT, 1)
gru_recurrent_kernel(const float* __restrict__ h0,
                     const int*   __restrict__ lengths,
                     const float* __restrict__ W_hh,
                     const float* __restrict__ b_hh) {
    extern __shared__ float sm[];
    int* len_s = (int*)(sm + OFF_LEN);
    const int tid = threadIdx.x;
    const int row0 = blockIdx.x * ROWS;

    if (tid < 100) sm[OFF_BHN + tid] = b_hh[200 + tid];
    for (int e = tid; e < ROWS * HH; e += RT) {
        int r = e / 100, j = e - r * 100;
        float hv = h0[(size_t)(row0 + r) * HH + j];
        sm[OFF_HS + j * ROWS + r] = hv;
        sm[OFF_H2 + r * HH + j]   = hv;
    }
    if (tid < ROWS) len_s[tid] = lengths[row0 + tid];

    const int kq = tid / 160;
    const int cp = tid - kq * 160;
    const bool act = (cp < 150);
    const int kbase = kq * 25;

    float wA[25], wB[25];
    if (act) {
        const float* pA = W_hh + cp * 100 + kbase;
        const float* pB = W_hh + (cp + 150) * 100 + kbase;
#pragma unroll
        for (int i = 0; i < 25; i++) { wA[i] = pA[i]; wB[i] = pB[i]; }
    }

    if (tid < 300) {
        unsigned int sa = (unsigned int)__cvta_generic_to_shared(sm + OFF_GI + tid * 4);
        const float* gp = g_gi + ((size_t)0 * BB + row0) * H3 + tid * 4;
        asm volatile("cp.async.ca.shared.global [%0], [%1], 16;" :: "r"(sa), "l"(gp));
    }
    asm volatile("cp.async.commit_group;");
    __syncthreads();

    int ml = len_s[0];
#pragma unroll
    for (int i = 1; i < ROWS; i++) ml = max(ml, len_s[i]);

    for (int t = 0; t < ml; t++) {
        const int buf = t & 1;
        const int nbuf = buf ^ 1;

        if (act) {
            const float* hsb = sm + OFF_HS + kbase * ROWS;
            u64 a0[2], a1[2];
            a0[0] = 0; a0[1] = 0; a1[0] = 0; a1[1] = 0;
#pragma unroll
            for (int i = 0; i < 25; i++) {
                u64 w0 = splat2(wA[i]);
                u64 w1 = splat2(wB[i]);
                ulonglong2 p = *(const ulonglong2*)(hsb + i * ROWS);
                a0[0] = fma2(w0, p.x, a0[0]); a0[1] = fma2(w0, p.y, a0[1]);
                a1[0] = fma2(w1, p.x, a1[0]); a1[1] = fma2(w1, p.y, a1[1]);
            }
            float* pgk = sm + OFF_PG + kq * 1200 + cp;
            float f0, f1;
            unpk(a0[0], f0, f1); pgk[0 * H3] = f0; pgk[1 * H3] = f1;
            unpk(a0[1], f0, f1); pgk[2 * H3] = f0; pgk[3 * H3] = f1;
            float* pgk2 = pgk + 150;
            unpk(a1[0], f0, f1); pgk2[0 * H3] = f0; pgk2[1 * H3] = f1;
            unpk(a1[1], f0, f1); pgk2[2 * H3] = f0; pgk2[3 * H3] = f1;
        }

        {
            int tp = (t + 1 < ml) ? (t + 1) : t;
            if (tid < 300) {
                unsigned int sa = (unsigned int)__cvta_generic_to_shared(
                    sm + OFF_GI + nbuf * 1200 + tid * 4);
                const float* gp = g_gi + ((size_t)tp * BB + row0) * H3 + tid * 4;
                asm volatile("cp.async.ca.shared.global [%0], [%1], 16;" :: "r"(sa), "l"(gp));
            }
            asm volatile("cp.async.commit_group;");
        }
        asm volatile("cp.async.wait_group 1;");
        __syncthreads();

        if (tid < ROWS * HH) {
            int o = tid;
            int r = o / 100;
            int j = o - r * 100;
            const float* pgr = sm + OFF_PG + r * H3 + j;
            float s_r = pgr[0]   + pgr[1200]       + pgr[2400]       + pgr[3600];
            float s_z = pgr[100] + pgr[1200 + 100] + pgr[2400 + 100] + pgr[3600 + 100];
            float s_n = pgr[200] + pgr[1200 + 200] + pgr[2400 + 200] + pgr[3600 + 200];
            const float* gs = sm + OFF_GI + buf * 1200 + r * H3 + j;
            float rg = sigmoid_f(gs[0] + s_r);
            float zg = sigmoid_f(gs[100] + s_z);
            float hn = s_n + sm[OFF_BHN + j];
            float nv = tanh_fast(fmaf(rg, hn, gs[200]));
            float hold = sm[OFF_H2 + r * HH + j];
            float hnew = fmaf(zg, hold - nv, nv);
            float hout = (t < len_s[r]) ? hnew : hold;
            sm[OFF_H2 + r * HH + j] = hout;
            sm[OFF_HS + j * ROWS + r] = hout;
            g_hidden[((size_t)t * BB + row0 + r) * HH + j] = hout;
        }
        __syncthreads();
    }
}

// ============================================================
// Epilogue: software-pipelined, unchanged from R9 (best).
// ============================================================
struct QS {
    float h[4][4];
    bool act[4];
    bool any;
};

__device__ __forceinline__ void loadq(QS& s, int q, int lane,
                                      const int* __restrict__ lengths) {
    int rid0 = q * 4;
    int t  = q >> 8;
    int b0 = rid0 & 1023;
    int L0 = lengths[b0];
    s.any = (t < L0);
    if (!s.any) return;
    s.act[0] = true;
    s.act[1] = t < lengths[b0 + 1];
    s.act[2] = t < lengths[b0 + 2];
    s.act[3] = t < lengths[b0 + 3];
#pragma unroll
    for (int i = 0; i < 4; i++) {
        const float* hp = g_hidden + (size_t)(rid0 + i) * HH;
        s.h[i][0] = hp[lane];
        s.h[i][1] = hp[lane + 32];
        s.h[i][2] = hp[lane + 64];
        s.h[i][3] = (lane < 4) ? hp[lane + 96] : 0.0f;
    }
}

__device__ __forceinline__ void procq(const QS& s, int q, int w, int lane,
                                      const float* Wo, float bo0, float bo1,
                                      float (*hq)[HH * 4],
                                      float* __restrict__ out) {
    int rid0 = q * 4;
    float* op = out + (size_t)rid0 * VV;
#pragma unroll
    for (int i = 0; i < 4; i++) {
        hq[w][lane * 4 + i]        = s.h[i][0];
        hq[w][(lane + 32) * 4 + i] = s.h[i][1];
        hq[w][(lane + 64) * 4 + i] = s.h[i][2];
        if (lane < 4) hq[w][(lane + 96) * 4 + i] = s.h[i][3];
    }
    __syncwarp();
    float acc0[4] = {0.f, 0.f, 0.f, 0.f};
    float acc1[4] = {0.f, 0.f, 0.f, 0.f};
#pragma unroll 5
    for (int k = 0; k < HH; k++) {
        float4 hv = *(const float4*)&hq[w][k * 4];
        float w0 = Wo[k * VV + lane];
        float w1 = Wo[k * VV + lane + 32];
        acc0[0] = fmaf(hv.x, w0, acc0[0]); acc1[0] = fmaf(hv.x, w1, acc1[0]);
        acc0[1] = fmaf(hv.y, w0, acc0[1]); acc1[1] = fmaf(hv.y, w1, acc1[1]);
        acc0[2] = fmaf(hv.z, w0, acc0[2]); acc1[2] = fmaf(hv.z, w1, acc1[2]);
        acc0[3] = fmaf(hv.w, w0, acc0[3]); acc1[3] = fmaf(hv.w, w1, acc1[3]);
    }
#pragma unroll
    for (int i = 0; i < 4; i++) {
        if (!s.act[i]) continue;
        float l0 = acc0[i] + bo0;
        float l1 = acc1[i] + bo1;
        float m = fmaxf(l0, l1);
#pragma unroll
        for (int sh = 16; sh; sh >>= 1) m = fmaxf(m, __shfl_xor_sync(0xffffffffu, m, sh));
        float se = __expf(l0 - m) + __expf(l1 - m);
#pragma unroll
        for (int sh = 16; sh; sh >>= 1) se += __shfl_xor_sync(0xffffffffu, se, sh);
        float lse = m + __logf(se);
        op[i * VV + lane]      = l0 - lse;
        op[i * VV + lane + 32] = l1 - lse;
    }
    __syncwarp();
}

__global__ void __launch_bounds__(256)
gru_output_kernel(const int*   __restrict__ lengths,
                  const float* __restrict__ W_out,
                  const float* __restrict__ b_out,
                  float*       __restrict__ out) {
    __shared__ float Wo[HH * VV];
    __shared__ float bo[VV];
    __shared__ float hq[8][HH * 4];
    const int tid = threadIdx.x;
    for (int e = tid; e < VV * HH; e += 256) {
        int cc = e / 100, k = e - cc * 100;
        Wo[k * VV + cc] = W_out[e];
    }
    if (tid < VV) bo[tid] = b_out[tid];
    __syncthreads();

    const int w = tid >> 5;
    const int lane = tid & 31;
    const float bo0 = bo[lane];
    const float bo1 = bo[lane + 32];
    const int nquad = (TT * BB) / 4;
    const int stride = gridDim.x * 8;

    QS A, B;
    int q = blockIdx.x * 8 + w;
    if (q < nquad) loadq(A, q, lane, lengths);
    while (q < nquad) {
        int qn = q + stride;
        if (qn < nquad) loadq(B, qn, lane, lengths);
        if (A.any) procq(A, q, w, lane, Wo, bo0, bo1, hq, out);
        q = qn;
        if (q >= nquad) break;
        qn = q + stride;
        if (qn < nquad) loadq(A, qn, lane, lengths);
        if (B.any) procq(B, q, w, lane, Wo, bo0, bo1, hq, out);
        q = qn;
    }
}

extern "C" void kernel_launch(void* const* d_in, const int* in_sizes, int n_in,
                              void* d_out, int out_size) {
    const float* x      = (const float*)d_in[0];
    const float* h0     = (const float*)d_in[1];
    const int*   lens   = (const int*)  d_in[2];
    const float* W_ih   = (const float*)d_in[3];
    const float* W_hh   = (const float*)d_in[4];
    const float* b_ih   = (const float*)d_in[5];
    const float* b_hh   = (const float*)d_in[6];
    const float* W_out  = (const float*)d_in[7];
    const float* b_out  = (const float*)d_in[8];
    float* out = (float*)d_out;

    cudaFuncSetAttribute(gi_precompute_kernel,
                         cudaFuncAttributeMaxDynamicSharedMemorySize, PRE_SMEM_FLOATS * 4);
    cudaFuncSetAttribute(gru_recurrent_kernel,
                         cudaFuncAttributeMaxDynamicSharedMemorySize, REC_SMEM_BYTES);

    cudaMemsetAsync(out, 0, (size_t)out_size * sizeof(float));
    gi_precompute_kernel<<<2 * TT, PT, PRE_SMEM_FLOATS * 4>>>(x, lens, W_ih, b_ih, b_hh);
    gru_recurrent_kernel<<<NBLK, RT, REC_SMEM_BYTES>>>(h0, lens, W_hh, b_hh);
    gru_output_kernel<<<2048, 256>>>(lens, W_out, b_out, out);
}

// round 13
// speedup vs baseline: 1.2835x; 1.0507x over previous
#include <cuda_runtime.h>
#include <cstdint>

#define TT 512
#define BB 1024
#define VV 64
#define HH 100
#define H3 300
#define ROWS 4
#define NBLK 256
#define RT 640
#define PT 320

// device scratch
__device__ float g_hidden[(size_t)TT * BB * HH];   // [t][b][j]  210 MB
__device__ float g_gi[(size_t)TT * BB * H3];       // [t][b][c]  630 MB (biases folded)

typedef unsigned long long u64;

__device__ __forceinline__ u64 splat2(float w) {
    u64 r; asm("mov.b64 %0, {%1, %1};" : "=l"(r) : "f"(w)); return r;
}
__device__ __forceinline__ u64 pack2(float lo, float hi) {
    u64 r; asm("mov.b64 %0, {%1, %2};" : "=l"(r) : "f"(lo), "f"(hi)); return r;
}
__device__ __forceinline__ u64 fma2(u64 a, u64 b, u64 c) {
    u64 d; asm("fma.rn.f32x2 %0, %1, %2, %3;" : "=l"(d) : "l"(a), "l"(b), "l"(c)); return d;
}
__device__ __forceinline__ void unpk(u64 v, float& lo, float& hi) {
    asm("mov.b64 {%0, %1}, %2;" : "=f"(lo), "=f"(hi) : "l"(v));
}
__device__ __forceinline__ float tanh_fast(float x) {
    float y; asm("tanh.approx.f32 %0, %1;" : "=f"(y) : "f"(x)); return y;
}
__device__ __forceinline__ float sigmoid_f(float x) {
    return 1.0f / (1.0f + __expf(-x));
}

// ============================================================
// Pre-kernel v4: gi = x@W_ih^T + biases.
// R6 pass structure (32-row passes, double-buffered transpose) but
// thread tile = 4 consecutive cols (float4 weight LDS.128) x 8 rows.
// 16 u64 accs -> no spill. grid = 1024 (t, half), 320 thr, 2 CTAs/SM.
// ============================================================
#define PRE_XS_STRIDE 36
#define PRE_XS_FLOATS (64 * PRE_XS_STRIDE)         // 2304
#define PRE_SMEM_FLOATS (19200 + 304 + 2 * PRE_XS_FLOATS)
__global__ void __launch_bounds__(PT, 2)
gi_precompute_kernel(const float* __restrict__ x,
                     const int*   __restrict__ lengths,
                     const float* __restrict__ W_ih,
                     const float* __restrict__ b_ih,
                     const float* __restrict__ b_hh) {
    extern __shared__ float sm[];
    __shared__ int s_npass;
    float* Wih_s = sm;                     // [64][300] Wih_s[v*300+c]
    float* bs    = sm + 19200;             // [300]+pad
    float* xs    = sm + 19504;             // [2][64][36]

    const int tid = threadIdx.x;
    const int t = blockIdx.x >> 1;
    const int rbase = (blockIdx.x & 1) * 512;

    if (tid == 0) {
        int lo = 0, hi = BB;
        while (lo < hi) {
            int m = (lo + hi) >> 1;
            if (lengths[m] > t) lo = m + 1; else hi = m;
        }
        int na = lo - rbase;
        na = na < 0 ? 0 : (na > 512 ? 512 : na);
        s_npass = (na + 31) >> 5;
    }
    __syncthreads();
    const int npass = s_npass;
    if (npass == 0) return;

    for (int e = tid; e < H3 * VV; e += PT) {
        int c = e >> 6, v = e & 63;
        Wih_s[v * H3 + c] = W_ih[e];
    }
    for (int c = tid; c < H3; c += PT)
        bs[c] = b_ih[c] + ((c < 200) ? b_hh[c] : 0.0f);

    const size_t xrow0 = (size_t)t * BB + rbase;
    // pass 0 x tile: 32 rows as pairs
    for (int e = tid; e < 1024; e += PT) {
        int rp = e >> 6, v = e & 63;
        float lo = x[(xrow0 + 2 * rp) * VV + v];
        float hi = x[(xrow0 + 2 * rp + 1) * VV + v];
        *(u64*)(xs + v * PRE_XS_STRIDE + rp * 2) = pack2(lo, hi);
    }
    __syncthreads();

    const int rq = tid / 80;               // 0..3 -> 8 rows each
    const int cg = tid - rq * 80;
    const bool act = (cg < 75);
    const int c0 = cg * 4;
    float4 bq = make_float4(0.f, 0.f, 0.f, 0.f);
    if (act) bq = *(const float4*)(bs + c0);

    for (int pass = 0; pass < npass; pass++) {
        const int buf = pass & 1;
        const bool has = (pass + 1 < npass);
        u64 pf[4];
        if (has) {
            const size_t base = (xrow0 + (pass + 1) * 32) * VV;
#pragma unroll
            for (int i = 0; i < 4; i++) {
                int e = tid + i * PT;
                if (e < 1024) {
                    int rp = e >> 6, v = e & 63;
                    float lo = x[base + (size_t)(2 * rp) * VV + v];
                    float hi = x[base + (size_t)(2 * rp + 1) * VV + v];
                    pf[i] = pack2(lo, hi);
                }
            }
        }
        if (act) {
            // accs: a[col][rowpair], 4 cols x 4 pairs = 16 u64
            u64 a0[4], a1[4], a2[4], a3[4];
#pragma unroll
            for (int i = 0; i < 4; i++) { a0[i] = 0; a1[i] = 0; a2[i] = 0; a3[i] = 0; }
            const float* wv = Wih_s + c0;
            const float* xb = xs + buf * PRE_XS_FLOATS + rq * 8;
#pragma unroll 4
            for (int v = 0; v < VV; v++) {
                float4 w4 = *(const float4*)(wv + v * H3);     // 1 LDS.128 -> 4 col weights
                u64 w0 = splat2(w4.x);
                u64 w1 = splat2(w4.y);
                u64 w2 = splat2(w4.z);
                u64 w3 = splat2(w4.w);
                ulonglong2 p = *(const ulonglong2*)(xb + v * PRE_XS_STRIDE);
                ulonglong2 q = *(const ulonglong2*)(xb + v * PRE_XS_STRIDE + 4);
                a0[0] = fma2(w0, p.x, a0[0]); a0[1] = fma2(w0, p.y, a0[1]);
                a0[2] = fma2(w0, q.x, a0[2]); a0[3] = fma2(w0, q.y, a0[3]);
                a1[0] = fma2(w1, p.x, a1[0]); a1[1] = fma2(w1, p.y, a1[1]);
                a1[2] = fma2(w1, q.x, a1[2]); a1[3] = fma2(w1, q.y, a1[3]);
                a2[0] = fma2(w2, p.x, a2[0]); a2[1] = fma2(w2, p.y, a2[1]);
                a2[2] = fma2(w2, q.x, a2[2]); a2[3] = fma2(w2, q.y, a2[3]);
                a3[0] = fma2(w3, p.x, a3[0]); a3[1] = fma2(w3, p.y, a3[1]);
                a3[2] = fma2(w3, q.x, a3[2]); a3[3] = fma2(w3, q.y, a3[3]);
            }
            const size_t rowbase = xrow0 + pass * 32 + rq * 8;
#pragma unroll
            for (int rp = 0; rp < 4; rp++) {
                float f00, f01, f10, f11, f20, f21, f30, f31;
                unpk(a0[rp], f00, f01);
                unpk(a1[rp], f10, f11);
                unpk(a2[rp], f20, f21);
                unpk(a3[rp], f30, f31);
                float4 o0 = make_float4(f00 + bq.x, f10 + bq.y, f20 + bq.z, f30 + bq.w);
                float4 o1 = make_float4(f01 + bq.x, f11 + bq.y, f21 + bq.z, f31 + bq.w);
                *(float4*)&g_gi[(rowbase + 2 * rp) * H3 + c0]     = o0;
                *(float4*)&g_gi[(rowbase + 2 * rp + 1) * H3 + c0] = o1;
            }
        }
        if (has) {
            float* xd = xs + (buf ^ 1) * PRE_XS_FLOATS;
#pragma unroll
            for (int i = 0; i < 4; i++) {
                int e = tid + i * PT;
                if (e < 1024) {
                    int rp = e >> 6, v = e & 63;
                    *(u64*)(xd + v * PRE_XS_STRIDE + rp * 2) = pf[i];
                }
            }
        }
        __syncthreads();
    }
}

// ============================================================
// Recurrent kernel: unchanged from R9 (best).
// ============================================================
#define OFF_HS 0
#define OFF_H2 400
#define OFF_PG 800
#define OFF_GI 5600
#define OFF_BHN 8000
#define OFF_LEN 8100
#define REC_SMEM_FLOATS (OFF_LEN + 4)
#define REC_SMEM_BYTES (REC_SMEM_FLOATS * 4)

__global__ void __launch_bounds__(RT, 1)
gru_recurrent_kernel(const float* __restrict__ h0,
                     const int*   __restrict__ lengths,
                     const float* __restrict__ W_hh,
                     const float* __restrict__ b_hh) {
    extern __shared__ float sm[];
    int* len_s = (int*)(sm + OFF_LEN);
    const int tid = threadIdx.x;
    const int row0 = blockIdx.x * ROWS;

    if (tid < 100) sm[OFF_BHN + tid] = b_hh[200 + tid];
    for (int e = tid; e < ROWS * HH; e += RT) {
        int r = e / 100, j = e - r * 100;
        float hv = h0[(size_t)(row0 + r) * HH + j];
        sm[OFF_HS + j * ROWS + r] = hv;
        sm[OFF_H2 + r * HH + j]   = hv;
    }
    if (tid < ROWS) len_s[tid] = lengths[row0 + tid];

    const int kq = tid / 160;
    const int cp = tid - kq * 160;
    const bool act = (cp < 150);
    const int kbase = kq * 25;

    float wA[25], wB[25];
    if (act) {
        const float* pA = W_hh + cp * 100 + kbase;
        const float* pB = W_hh + (cp + 150) * 100 + kbase;
#pragma unroll
        for (int i = 0; i < 25; i++) { wA[i] = pA[i]; wB[i] = pB[i]; }
    }

    if (tid < 300) {
        unsigned int sa = (unsigned int)__cvta_generic_to_shared(sm + OFF_GI + tid * 4);
        const float* gp = g_gi + ((size_t)0 * BB + row0) * H3 + tid * 4;
        asm volatile("cp.async.ca.shared.global [%0], [%1], 16;" :: "r"(sa), "l"(gp));
    }
    asm volatile("cp.async.commit_group;");
    __syncthreads();

    int ml = len_s[0];
#pragma unroll
    for (int i = 1; i < ROWS; i++) ml = max(ml, len_s[i]);

    for (int t = 0; t < ml; t++) {
        const int buf = t & 1;
        const int nbuf = buf ^ 1;

        if (act) {
            const float* hsb = sm + OFF_HS + kbase * ROWS;
            u64 a0[2], a1[2];
            a0[0] = 0; a0[1] = 0; a1[0] = 0; a1[1] = 0;
#pragma unroll
            for (int i = 0; i < 25; i++) {
                u64 w0 = splat2(wA[i]);
                u64 w1 = splat2(wB[i]);
                ulonglong2 p = *(const ulonglong2*)(hsb + i * ROWS);
                a0[0] = fma2(w0, p.x, a0[0]); a0[1] = fma2(w0, p.y, a0[1]);
                a1[0] = fma2(w1, p.x, a1[0]); a1[1] = fma2(w1, p.y, a1[1]);
            }
            float* pgk = sm + OFF_PG + kq * 1200 + cp;
            float f0, f1;
            unpk(a0[0], f0, f1); pgk[0 * H3] = f0; pgk[1 * H3] = f1;
            unpk(a0[1], f0, f1); pgk[2 * H3] = f0; pgk[3 * H3] = f1;
            float* pgk2 = pgk + 150;
            unpk(a1[0], f0, f1); pgk2[0 * H3] = f0; pgk2[1 * H3] = f1;
            unpk(a1[1], f0, f1); pgk2[2 * H3] = f0; pgk2[3 * H3] = f1;
        }

        {
            int tp = (t + 1 < ml) ? (t + 1) : t;
            if (tid < 300) {
                unsigned int sa = (unsigned int)__cvta_generic_to_shared(
                    sm + OFF_GI + nbuf * 1200 + tid * 4);
                const float* gp = g_gi + ((size_t)tp * BB + row0) * H3 + tid * 4;
                asm volatile("cp.async.ca.shared.global [%0], [%1], 16;" :: "r"(sa), "l"(gp));
            }
            asm volatile("cp.async.commit_group;");
        }
        asm volatile("cp.async.wait_group 1;");
        __syncthreads();

        if (tid < ROWS * HH) {
            int o = tid;
            int r = o / 100;
            int j = o - r * 100;
            const float* pgr = sm + OFF_PG + r * H3 + j;
            float s_r = pgr[0]   + pgr[1200]       + pgr[2400]       + pgr[3600];
            float s_z = pgr[100] + pgr[1200 + 100] + pgr[2400 + 100] + pgr[3600 + 100];
            float s_n = pgr[200] + pgr[1200 + 200] + pgr[2400 + 200] + pgr[3600 + 200];
            const float* gs = sm + OFF_GI + buf * 1200 + r * H3 + j;
            float rg = sigmoid_f(gs[0] + s_r);
            float zg = sigmoid_f(gs[100] + s_z);
            float hn = s_n + sm[OFF_BHN + j];
            float nv = tanh_fast(fmaf(rg, hn, gs[200]));
            float hold = sm[OFF_H2 + r * HH + j];
            float hnew = fmaf(zg, hold - nv, nv);
            float hout = (t < len_s[r]) ? hnew : hold;
            sm[OFF_H2 + r * HH + j] = hout;
            sm[OFF_HS + j * ROWS + r] = hout;
            g_hidden[((size_t)t * BB + row0 + r) * HH + j] = hout;
        }
        __syncthreads();
    }
}

// ============================================================
// Epilogue: software-pipelined, unchanged from R9 (best).
// ============================================================
struct QS {
    float h[4][4];
    bool act[4];
    bool any;
};

__device__ __forceinline__ void loadq(QS& s, int q, int lane,
                                      const int* __restrict__ lengths) {
    int rid0 = q * 4;
    int t  = q >> 8;
    int b0 = rid0 & 1023;
    int L0 = lengths[b0];
    s.any = (t < L0);
    if (!s.any) return;
    s.act[0] = true;
    s.act[1] = t < lengths[b0 + 1];
    s.act[2] = t < lengths[b0 + 2];
    s.act[3] = t < lengths[b0 + 3];
#pragma unroll
    for (int i = 0; i < 4; i++) {
        const float* hp = g_hidden + (size_t)(rid0 + i) * HH;
        s.h[i][0] = hp[lane];
        s.h[i][1] = hp[lane + 32];
        s.h[i][2] = hp[lane + 64];
        s.h[i][3] = (lane < 4) ? hp[lane + 96] : 0.0f;
    }
}

__device__ __forceinline__ void procq(const QS& s, int q, int w, int lane,
                                      const float* Wo, float bo0, float bo1,
                                      float (*hq)[HH * 4],
                                      float* __restrict__ out) {
    int rid0 = q * 4;
    float* op = out + (size_t)rid0 * VV;
#pragma unroll
    for (int i = 0; i < 4; i++) {
        hq[w][lane * 4 + i]        = s.h[i][0];
        hq[w][(lane + 32) * 4 + i] = s.h[i][1];
        hq[w][(lane + 64) * 4 + i] = s.h[i][2];
        if (lane < 4) hq[w][(lane + 96) * 4 + i] = s.h[i][3];
    }
    __syncwarp();
    float acc0[4] = {0.f, 0.f, 0.f, 0.f};
    float acc1[4] = {0.f, 0.f, 0.f, 0.f};
#pragma unroll 5
    for (int k = 0; k < HH; k++) {
        float4 hv = *(const float4*)&hq[w][k * 4];
        float w0 = Wo[k * VV + lane];
        float w1 = Wo[k * VV + lane + 32];
        acc0[0] = fmaf(hv.x, w0, acc0[0]); acc1[0] = fmaf(hv.x, w1, acc1[0]);
        acc0[1] = fmaf(hv.y, w0, acc0[1]); acc1[1] = fmaf(hv.y, w1, acc1[1]);
        acc0[2] = fmaf(hv.z, w0, acc0[2]); acc1[2] = fmaf(hv.z, w1, acc1[2]);
        acc0[3] = fmaf(hv.w, w0, acc0[3]); acc1[3] = fmaf(hv.w, w1, acc1[3]);
    }
#pragma unroll
    for (int i = 0; i < 4; i++) {
        if (!s.act[i]) continue;
        float l0 = acc0[i] + bo0;
        float l1 = acc1[i] + bo1;
        float m = fmaxf(l0, l1);
#pragma unroll
        for (int sh = 16; sh; sh >>= 1) m = fmaxf(m, __shfl_xor_sync(0xffffffffu, m, sh));
        float se = __expf(l0 - m) + __expf(l1 - m);
#pragma unroll
        for (int sh = 16; sh; sh >>= 1) se += __shfl_xor_sync(0xffffffffu, se, sh);
        float lse = m + __logf(se);
        op[i * VV + lane]      = l0 - lse;
        op[i * VV + lane + 32] = l1 - lse;
    }
    __syncwarp();
}

__global__ void __launch_bounds__(256)
gru_output_kernel(const int*   __restrict__ lengths,
                  const float* __restrict__ W_out,
                  const float* __restrict__ b_out,
                  float*       __restrict__ out) {
    __shared__ float Wo[HH * VV];
    __shared__ float bo[VV];
    __shared__ float hq[8][HH * 4];
    const int tid = threadIdx.x;
    for (int e = tid; e < VV * HH; e += 256) {
        int cc = e / 100, k = e - cc * 100;
        Wo[k * VV + cc] = W_out[e];
    }
    if (tid < VV) bo[tid] = b_out[tid];
    __syncthreads();

    const int w = tid >> 5;
    const int lane = tid & 31;
    const float bo0 = bo[lane];
    const float bo1 = bo[lane + 32];
    const int nquad = (TT * BB) / 4;
    const int stride = gridDim.x * 8;

    QS A, B;
    int q = blockIdx.x * 8 + w;
    if (q < nquad) loadq(A, q, lane, lengths);
    while (q < nquad) {
        int qn = q + stride;
        if (qn < nquad) loadq(B, qn, lane, lengths);
        if (A.any) procq(A, q, w, lane, Wo, bo0, bo1, hq, out);
        q = qn;
        if (q >= nquad) break;
        qn = q + stride;
        if (qn < nquad) loadq(A, qn, lane, lengths);
        if (B.any) procq(B, q, w, lane, Wo, bo0, bo1, hq, out);
        q = qn;
    }
}

extern "C" void kernel_launch(void* const* d_in, const int* in_sizes, int n_in,
                              void* d_out, int out_size) {
    const float* x      = (const float*)d_in[0];
    const float* h0     = (const float*)d_in[1];
    const int*   lens   = (const int*)  d_in[2];
    const float* W_ih   = (const float*)d_in[3];
    const float* W_hh   = (const float*)d_in[4];
    const float* b_ih   = (const float*)d_in[5];
    const float* b_hh   = (const float*)d_in[6];
    const float* W_out  = (const float*)d_in[7];
    const float* b_out  = (const float*)d_in[8];
    float* out = (float*)d_out;

    cudaFuncSetAttribute(gi_precompute_kernel,
                         cudaFuncAttributeMaxDynamicSharedMemorySize, PRE_SMEM_FLOATS * 4);
    cudaFuncSetAttribute(gru_recurrent_kernel,
                         cudaFuncAttributeMaxDynamicSharedMemorySize, REC_SMEM_BYTES);

    cudaMemsetAsync(out, 0, (size_t)out_size * sizeof(float));
    gi_precompute_kernel<<<2 * TT, PT, PRE_SMEM_FLOATS * 4>>>(x, lens, W_ih, b_ih, b_hh);
    gru_recurrent_kernel<<<NBLK, RT, REC_SMEM_BYTES>>>(h0, lens, W_hh, b_hh);
    gru_output_kernel<<<2048, 256>>>(lens, W_out, b_out, out);
}